// round 7
// baseline (speedup 1.0000x reference)
#include <cuda_runtime.h>
#include <cuda_bf16.h>
#include <cstdint>

#define N_ITEMS 30000
#define N_USERS 20000
#define NNODES  50000
#define NEDGES  512000
#define D0 768
#define D1 128
#define D2 64
#define OUTW 960   // 768 + 128 + 64

// ---------------- device scratch (static, no runtime alloc) ----------------
__device__ float g_side0[(size_t)NNODES * D0];   // 153.6 MB
__device__ float g_ego1 [(size_t)NNODES * D1];   // 25.6 MB
__device__ float g_side1[(size_t)NNODES * D1];   // 25.6 MB
__device__ int   g_hist[NNODES];
__device__ int   g_rowptr[NNODES + 1];
__device__ int   g_cursor[NNODES];
__device__ int   g_col_sorted[NEDGES];
__device__ float g_val_sorted[NEDGES];
// split + transposed weights for tensor-core gemm0: [N=128][K=768] bf16
__device__ __nv_bfloat16 g_w1hiT[D1 * D0];
__device__ __nv_bfloat16 g_w1loT[D1 * D0];
__device__ __nv_bfloat16 g_w2hiT[D1 * D0];
__device__ __nv_bfloat16 g_w2loT[D1 * D0];

__device__ __forceinline__ float leaky(float v) { return v > 0.f ? v : 0.01f * v; }

__device__ __forceinline__ uint32_t smem_u32(const void* p) {
    uint32_t a;
    asm("{ .reg .u64 t; cvta.to.shared.u64 t, %1; cvt.u32.u64 %0, t; }"
        : "=r"(a) : "l"(p));
    return a;
}
__device__ __forceinline__ void ldsm_x4(uint32_t* r, uint32_t addr) {
    asm volatile("ldmatrix.sync.aligned.m8n8.x4.shared.b16 {%0,%1,%2,%3}, [%4];"
                 : "=r"(r[0]), "=r"(r[1]), "=r"(r[2]), "=r"(r[3]) : "r"(addr));
}
__device__ __forceinline__ void ldsm_x2(uint32_t* r, uint32_t addr) {
    asm volatile("ldmatrix.sync.aligned.m8n8.x2.shared.b16 {%0,%1}, [%2];"
                 : "=r"(r[0]), "=r"(r[1]) : "r"(addr));
}
__device__ __forceinline__ void mma_bf16(float* d, const uint32_t* a, const uint32_t* b) {
    asm volatile(
        "mma.sync.aligned.m16n8k16.row.col.f32.bf16.bf16.f32 "
        "{%0,%1,%2,%3}, {%4,%5,%6,%7}, {%8,%9}, {%0,%1,%2,%3};"
        : "+f"(d[0]), "+f"(d[1]), "+f"(d[2]), "+f"(d[3])
        : "r"(a[0]), "r"(a[1]), "r"(a[2]), "r"(a[3]), "r"(b[0]), "r"(b[1]));
}
__device__ __forceinline__ uint32_t pack_bf16(__nv_bfloat16 a, __nv_bfloat16 b) {
    return ((uint32_t)__bfloat16_as_ushort(b) << 16) | (uint32_t)__bfloat16_as_ushort(a);
}
__device__ __forceinline__ void split_bf16(float x, __nv_bfloat16& hi, __nv_bfloat16& lo) {
    hi = __float2bfloat16(x);
    lo = __float2bfloat16(x - __bfloat162float(hi));
}

// ---------------- CSR build ----------------
__global__ void init_hist_kernel() {
    for (int i = blockIdx.x * blockDim.x + threadIdx.x; i < NNODES;
         i += gridDim.x * blockDim.x)
        g_hist[i] = 0;
}

__global__ void hist_kernel(const int* __restrict__ rows) {
    int e = blockIdx.x * blockDim.x + threadIdx.x;
    if (e < NEDGES) atomicAdd(&g_hist[rows[e]], 1);
}

__global__ void scan_kernel() {
    __shared__ int wsum[32];
    int tid = threadIdx.x, lane = tid & 31, wid = tid >> 5;
    int running = 0;
    for (int base = 0; base < NNODES; base += 1024) {
        int i = base + tid;
        int v = (i < NNODES) ? g_hist[i] : 0;
        int x = v;
        #pragma unroll
        for (int off = 1; off < 32; off <<= 1) {
            int t = __shfl_up_sync(0xffffffffu, x, off);
            if (lane >= off) x += t;
        }
        if (lane == 31) wsum[wid] = x;
        __syncthreads();
        if (wid == 0) {
            int w = wsum[lane];
            #pragma unroll
            for (int off = 1; off < 32; off <<= 1) {
                int t = __shfl_up_sync(0xffffffffu, w, off);
                if (lane >= off) w += t;
            }
            wsum[lane] = w;
        }
        __syncthreads();
        int warp_off = (wid == 0) ? 0 : wsum[wid - 1];
        int incl = x + warp_off;
        int total = wsum[31];
        if (i < NNODES) {
            int ex = running + incl - v;
            g_rowptr[i] = ex;
            g_cursor[i] = ex;
        }
        running += total;
        __syncthreads();
    }
    if (tid == 0) g_rowptr[NNODES] = running;
}

__global__ void scatter_kernel(const int* __restrict__ rows,
                               const int* __restrict__ cols,
                               const float* __restrict__ vals) {
    int e = blockIdx.x * blockDim.x + threadIdx.x;
    if (e < NEDGES) {
        int r = rows[e];
        int p = atomicAdd(&g_cursor[r], 1);
        g_col_sorted[p] = cols[e];
        g_val_sorted[p] = vals[e];
    }
}

// ---------------- W split+transpose prep ----------------
__global__ void wsplit_kernel(const float* __restrict__ W1,
                              const float* __restrict__ W2) {
    int idx = blockIdx.x * blockDim.x + threadIdx.x;   // over 128*768, k fast
    if (idx >= D1 * D0) return;
    int n = idx / D0, k = idx - n * D0;
    float w1 = W1[(size_t)k * D1 + n];
    float w2 = W2[(size_t)k * D1 + n];
    __nv_bfloat16 hi, lo;
    split_bf16(w1, hi, lo);
    g_w1hiT[idx] = hi; g_w1loT[idx] = lo;
    split_bf16(w2, hi, lo);
    g_w2hiT[idx] = hi; g_w2loT[idx] = lo;
}

// ---------------- SpMM layer0 (feature-chunked, 256-wide, 8 loads in flight) --
// side0[:, kt:kt+256] = A @ ego0[:, kt:kt+256]; blockIdx.y = chunk (slow dim).
__global__ __launch_bounds__(256) void spmm0_chunk_kernel(
    const float* __restrict__ item, const float* __restrict__ user) {
    const int w = threadIdx.x >> 5;      // warp -> row
    const int lane = threadIdx.x & 31;   // lane -> cols off, off+128
    const int r = blockIdx.x * 8 + w;
    const int off = blockIdx.y * 256 + lane * 4;
    if (r >= NNODES) return;
    const int e0 = g_rowptr[r], e1 = g_rowptr[r + 1];
    float4 accA = make_float4(0.f, 0.f, 0.f, 0.f);
    float4 accB = make_float4(0.f, 0.f, 0.f, 0.f);
    int e = e0;
    const int n4 = e0 + ((e1 - e0) & ~3);
    for (; e < n4; e += 4) {
        int c0 = g_col_sorted[e + 0], c1 = g_col_sorted[e + 1];
        int c2 = g_col_sorted[e + 2], c3 = g_col_sorted[e + 3];
        float v0 = g_val_sorted[e + 0], v1 = g_val_sorted[e + 1];
        float v2 = g_val_sorted[e + 2], v3 = g_val_sorted[e + 3];
        const float* p0 = ((c0 < N_ITEMS) ? item + (size_t)c0 * D0
                                          : user + (size_t)(c0 - N_ITEMS) * D0) + off;
        const float* p1 = ((c1 < N_ITEMS) ? item + (size_t)c1 * D0
                                          : user + (size_t)(c1 - N_ITEMS) * D0) + off;
        const float* p2 = ((c2 < N_ITEMS) ? item + (size_t)c2 * D0
                                          : user + (size_t)(c2 - N_ITEMS) * D0) + off;
        const float* p3 = ((c3 < N_ITEMS) ? item + (size_t)c3 * D0
                                          : user + (size_t)(c3 - N_ITEMS) * D0) + off;
        float4 a0 = __ldg((const float4*)p0);
        float4 b0 = __ldg((const float4*)(p0 + 128));
        float4 a1 = __ldg((const float4*)p1);
        float4 b1 = __ldg((const float4*)(p1 + 128));
        float4 a2 = __ldg((const float4*)p2);
        float4 b2 = __ldg((const float4*)(p2 + 128));
        float4 a3 = __ldg((const float4*)p3);
        float4 b3 = __ldg((const float4*)(p3 + 128));
        accA.x += v0 * a0.x + v1 * a1.x + v2 * a2.x + v3 * a3.x;
        accA.y += v0 * a0.y + v1 * a1.y + v2 * a2.y + v3 * a3.y;
        accA.z += v0 * a0.z + v1 * a1.z + v2 * a2.z + v3 * a3.z;
        accA.w += v0 * a0.w + v1 * a1.w + v2 * a2.w + v3 * a3.w;
        accB.x += v0 * b0.x + v1 * b1.x + v2 * b2.x + v3 * b3.x;
        accB.y += v0 * b0.y + v1 * b1.y + v2 * b2.y + v3 * b3.y;
        accB.z += v0 * b0.z + v1 * b1.z + v2 * b2.z + v3 * b3.z;
        accB.w += v0 * b0.w + v1 * b1.w + v2 * b2.w + v3 * b3.w;
    }
    for (; e < e1; ++e) {
        int   c = g_col_sorted[e];
        float v = g_val_sorted[e];
        const float* p = ((c < N_ITEMS) ? item + (size_t)c * D0
                                        : user + (size_t)(c - N_ITEMS) * D0) + off;
        float4 a = __ldg((const float4*)p);
        float4 b = __ldg((const float4*)(p + 128));
        accA.x += v * a.x; accA.y += v * a.y; accA.z += v * a.z; accA.w += v * a.w;
        accB.x += v * b.x; accB.y += v * b.y; accB.z += v * b.z; accB.w += v * b.w;
    }
    *(float4*)(g_side0 + (size_t)r * D0 + off) = accA;
    *(float4*)(g_side0 + (size_t)r * D0 + off + 128) = accB;
}

// ---------------- fused GEMM layer0 (mma.sync bf16, 3-term split) ----------------
// ego1 = leaky((side0+ego0)@W1 + b1 + (side0*ego0)@W2 + b2)
// Streams ego0 -> out[:, 0:768]; fuses row-normalize -> out[:, 768:896].
// BM=64, BN=128, BK=16, 128 threads (4 warps 2x2, warp tile 32x64)
#define APAD 24   // row stride in bf16 (48 B, conflict-free ldmatrix)

__global__ __launch_bounds__(128) void gemm0_mma_kernel(
    const float* __restrict__ item, const float* __restrict__ user,
    const float* __restrict__ b1, const float* __restrict__ b2,
    float* __restrict__ out) {
    __shared__ __align__(16) __nv_bfloat16 sAhi[64 * APAD];
    __shared__ __align__(16) __nv_bfloat16 sAlo[64 * APAD];
    __shared__ __align__(16) __nv_bfloat16 sHhi[64 * APAD];
    __shared__ __align__(16) __nv_bfloat16 sHlo[64 * APAD];
    __shared__ __align__(16) __nv_bfloat16 sW1h[128 * APAD];
    __shared__ __align__(16) __nv_bfloat16 sW1l[128 * APAD];
    __shared__ __align__(16) __nv_bfloat16 sW2h[128 * APAD];
    __shared__ __align__(16) __nv_bfloat16 sW2l[128 * APAD];
    __shared__ float bsum[D1];
    __shared__ float rowss[64];

    const int t    = threadIdx.x;
    const int lane = t & 31;
    const int wid  = t >> 5;
    const int wm   = wid >> 1;           // 0..1 -> M offset wm*32
    const int wn   = wid & 1;            // 0..1 -> N offset wn*64
    const int rm   = blockIdx.x * 64;

    bsum[t] = b1[t] + b2[t];
    if (t < 64) rowss[t] = 0.f;

    // per-thread staging coords
    const int arow = t >> 1;             // 0..63
    const int akq  = (t & 1) * 8;        // 0 or 8
    const int gm   = rm + arow;
    const bool mOk = gm < NNODES;
    const float* sideRow = g_side0 + (size_t)gm * D0 + akq;
    const float* egoRow  = ((gm < N_ITEMS) ? item + (size_t)gm * D0
                                           : user + (size_t)(gm - N_ITEMS) * D0) + akq;
    float* outRow = out + (size_t)gm * OUTW + akq;

    // ldmatrix addresses (constant across k-chunks)
    const uint32_t aOff = (uint32_t)(((wm * 32 + (lane & 15)) * APAD + (lane >> 4) * 8) * 2);
    const uint32_t addrAhi = smem_u32(sAhi) + aOff;
    const uint32_t addrAlo = smem_u32(sAlo) + aOff;
    const uint32_t addrHhi = smem_u32(sHhi) + aOff;
    const uint32_t addrHlo = smem_u32(sHlo) + aOff;
    const uint32_t bOff = (uint32_t)(((wn * 64 + (lane & 7)) * APAD + ((lane >> 3) & 1) * 8) * 2);
    const uint32_t addrW1h = smem_u32(sW1h) + bOff;
    const uint32_t addrW1l = smem_u32(sW1l) + bOff;
    const uint32_t addrW2h = smem_u32(sW2h) + bOff;
    const uint32_t addrW2l = smem_u32(sW2l) + bOff;
    const uint32_t MT = 16 * APAD * 2;   // m-tile stride bytes
    const uint32_t JT = 8 * APAD * 2;    // n-tile stride bytes

    float acc[2][8][4];
    #pragma unroll
    for (int i = 0; i < 2; ++i)
        #pragma unroll
        for (int j = 0; j < 8; ++j)
            #pragma unroll
            for (int q = 0; q < 4; ++q) acc[i][j][q] = 0.f;

    for (int kt = 0; kt < D0; kt += 16) {
        // ---- stage A variants (+ stream ego to out[:, 0:768]) ----
        {
            float4 sa, sb, ea, eb;
            if (mOk) {
                sa = __ldg((const float4*)(sideRow + kt));
                sb = __ldg((const float4*)(sideRow + kt + 4));
                ea = __ldg((const float4*)(egoRow + kt));
                eb = __ldg((const float4*)(egoRow + kt + 4));
                *(float4*)(outRow + kt) = ea;
                *(float4*)(outRow + kt + 4) = eb;
            } else {
                sa = make_float4(0.f, 0.f, 0.f, 0.f);
                sb = sa; ea = sa; eb = sa;
            }
            float av[8] = {sa.x + ea.x, sa.y + ea.y, sa.z + ea.z, sa.w + ea.w,
                           sb.x + eb.x, sb.y + eb.y, sb.z + eb.z, sb.w + eb.w};
            float hv[8] = {sa.x * ea.x, sa.y * ea.y, sa.z * ea.z, sa.w * ea.w,
                           sb.x * eb.x, sb.y * eb.y, sb.z * eb.z, sb.w * eb.w};
            uint4 uahi, ualo, uhhi, uhlo;
            uint32_t* pa = (uint32_t*)&uahi; uint32_t* pl = (uint32_t*)&ualo;
            uint32_t* ph = (uint32_t*)&uhhi; uint32_t* pm = (uint32_t*)&uhlo;
            __nv_bfloat16 h0, l0, h1, l1;
            #pragma unroll
            for (int q = 0; q < 4; ++q) {
                split_bf16(av[2 * q], h0, l0);
                split_bf16(av[2 * q + 1], h1, l1);
                pa[q] = pack_bf16(h0, h1);
                pl[q] = pack_bf16(l0, l1);
                split_bf16(hv[2 * q], h0, l0);
                split_bf16(hv[2 * q + 1], h1, l1);
                ph[q] = pack_bf16(h0, h1);
                pm[q] = pack_bf16(l0, l1);
            }
            int d = arow * APAD + akq;
            *(uint4*)(sAhi + d) = uahi;
            *(uint4*)(sAlo + d) = ualo;
            *(uint4*)(sHhi + d) = uhhi;
            *(uint4*)(sHlo + d) = uhlo;
        }
        // ---- stage W variants ----
        #pragma unroll
        for (int s = 0; s < 2; ++s) {
            int g = s * 128 + t;
            int n = g >> 1;
            int kq = (g & 1) * 8;
            size_t src = (size_t)n * D0 + kt + kq;
            int d = n * APAD + kq;
            *(uint4*)(sW1h + d) = __ldg((const uint4*)(g_w1hiT + src));
            *(uint4*)(sW1l + d) = __ldg((const uint4*)(g_w1loT + src));
            *(uint4*)(sW2h + d) = __ldg((const uint4*)(g_w2hiT + src));
            *(uint4*)(sW2l + d) = __ldg((const uint4*)(g_w2loT + src));
        }
        __syncthreads();

        // ---- A fragments (4 variants x 2 m-tiles) ----
        uint32_t fAhi[2][4], fAlo[2][4], fHhi[2][4], fHlo[2][4];
        ldsm_x4(fAhi[0], addrAhi);       ldsm_x4(fAhi[1], addrAhi + MT);
        ldsm_x4(fAlo[0], addrAlo);       ldsm_x4(fAlo[1], addrAlo + MT);
        ldsm_x4(fHhi[0], addrHhi);       ldsm_x4(fHhi[1], addrHhi + MT);
        ldsm_x4(fHlo[0], addrHlo);       ldsm_x4(fHlo[1], addrHlo + MT);

        #pragma unroll
        for (int j = 0; j < 8; ++j) {
            uint32_t b[2];
            ldsm_x2(b, addrW1h + j * JT);
            mma_bf16(acc[0][j], fAhi[0], b);
            mma_bf16(acc[1][j], fAhi[1], b);
            mma_bf16(acc[0][j], fAlo[0], b);
            mma_bf16(acc[1][j], fAlo[1], b);
            ldsm_x2(b, addrW1l + j * JT);
            mma_bf16(acc[0][j], fAhi[0], b);
            mma_bf16(acc[1][j], fAhi[1], b);
            ldsm_x2(b, addrW2h + j * JT);
            mma_bf16(acc[0][j], fHhi[0], b);
            mma_bf16(acc[1][j], fHhi[1], b);
            mma_bf16(acc[0][j], fHlo[0], b);
            mma_bf16(acc[1][j], fHlo[1], b);
            ldsm_x2(b, addrW2l + j * JT);
            mma_bf16(acc[0][j], fHhi[0], b);
            mma_bf16(acc[1][j], fHhi[1], b);
        }
        __syncthreads();
    }

    // ---- epilogue: bias + leaky -> regs, row sum-of-squares -> smem ----
    float vals[2][8][4];
    #pragma unroll
    for (int mt = 0; mt < 2; ++mt) {
        float s0 = 0.f, s1 = 0.f;
        #pragma unroll
        for (int j = 0; j < 8; ++j) {
            int col = wn * 64 + j * 8 + (lane & 3) * 2;
            float bc0 = bsum[col], bc1 = bsum[col + 1];
            float v0 = leaky(acc[mt][j][0] + bc0);
            float v1 = leaky(acc[mt][j][1] + bc1);
            float v2 = leaky(acc[mt][j][2] + bc0);
            float v3 = leaky(acc[mt][j][3] + bc1);
            vals[mt][j][0] = v0; vals[mt][j][1] = v1;
            vals[mt][j][2] = v2; vals[mt][j][3] = v3;
            s0 += v0 * v0 + v1 * v1;
            s1 += v2 * v2 + v3 * v3;
        }
        int lr0 = wm * 32 + mt * 16 + (lane >> 2);
        atomicAdd(&rowss[lr0], s0);
        atomicAdd(&rowss[lr0 + 8], s1);
    }
    __syncthreads();

    // ---- write raw ego1 + normalized out[:, 768:896] ----
    #pragma unroll
    for (int mt = 0; mt < 2; ++mt) {
        int lr0 = wm * 32 + mt * 16 + (lane >> 2);
        int row0 = rm + lr0;
        int row1 = row0 + 8;
        float inv0 = 1.f / fmaxf(sqrtf(rowss[lr0]), 1e-12f);
        float inv1 = 1.f / fmaxf(sqrtf(rowss[lr0 + 8]), 1e-12f);
        #pragma unroll
        for (int j = 0; j < 8; ++j) {
            int col = wn * 64 + j * 8 + (lane & 3) * 2;
            if (row0 < NNODES) {
                float2 o = make_float2(vals[mt][j][0], vals[mt][j][1]);
                *(float2*)(g_ego1 + (size_t)row0 * D1 + col) = o;
                float2 n = make_float2(o.x * inv0, o.y * inv0);
                *(float2*)(out + (size_t)row0 * OUTW + D0 + col) = n;
            }
            if (row1 < NNODES) {
                float2 o = make_float2(vals[mt][j][2], vals[mt][j][3]);
                *(float2*)(g_ego1 + (size_t)row1 * D1 + col) = o;
                float2 n = make_float2(o.x * inv1, o.y * inv1);
                *(float2*)(out + (size_t)row1 * OUTW + D0 + col) = n;
            }
        }
    }
}

// ---------------- SpMM layer1: side1 = A @ ego1 (unroll 4) ----------------
__global__ void spmm1_kernel() {
    int w = threadIdx.x >> 5;
    int lane = threadIdx.x & 31;
    int r = blockIdx.x * 4 + w;
    if (r >= NNODES) return;
    int e0 = g_rowptr[r], e1 = g_rowptr[r + 1];
    float4 acc = make_float4(0.f, 0.f, 0.f, 0.f);
    int e = e0;
    int n4 = e0 + ((e1 - e0) & ~3);
    for (; e < n4; e += 4) {
        int c0 = g_col_sorted[e + 0], c1 = g_col_sorted[e + 1];
        int c2 = g_col_sorted[e + 2], c3 = g_col_sorted[e + 3];
        float v0 = g_val_sorted[e + 0], v1 = g_val_sorted[e + 1];
        float v2 = g_val_sorted[e + 2], v3 = g_val_sorted[e + 3];
        float4 x0 = __ldg((const float4*)g_ego1 + (size_t)c0 * (D1 / 4) + lane);
        float4 x1 = __ldg((const float4*)g_ego1 + (size_t)c1 * (D1 / 4) + lane);
        float4 x2 = __ldg((const float4*)g_ego1 + (size_t)c2 * (D1 / 4) + lane);
        float4 x3 = __ldg((const float4*)g_ego1 + (size_t)c3 * (D1 / 4) + lane);
        acc.x += v0 * x0.x + v1 * x1.x + v2 * x2.x + v3 * x3.x;
        acc.y += v0 * x0.y + v1 * x1.y + v2 * x2.y + v3 * x3.y;
        acc.z += v0 * x0.z + v1 * x1.z + v2 * x2.z + v3 * x3.z;
        acc.w += v0 * x0.w + v1 * x1.w + v2 * x2.w + v3 * x3.w;
    }
    for (; e < e1; ++e) {
        int   c = g_col_sorted[e];
        float v = g_val_sorted[e];
        float4 x = __ldg((const float4*)g_ego1 + (size_t)c * (D1 / 4) + lane);
        acc.x += v * x.x; acc.y += v * x.y; acc.z += v * x.z; acc.w += v * x.w;
    }
    ((float4*)g_side1)[(size_t)r * (D1 / 4) + lane] = acc;
}

// ---------------- fused GEMM layer1 + normalize -> out[:, 896:960] ----------------
__global__ __launch_bounds__(256) void gemm1_kernel(
    const float* __restrict__ W1, const float* __restrict__ b1,
    const float* __restrict__ W2, const float* __restrict__ b2,
    float* __restrict__ out) {
    __shared__ __align__(16) float As[16][68];
    __shared__ __align__(16) float Hs[16][68];
    __shared__ __align__(16) float W1s[16][64];
    __shared__ __align__(16) float W2s[16][64];

    int t  = threadIdx.x;
    int tx = t & 31, ty = t >> 5;
    int rm = blockIdx.x * 64;

    float acc[8][2];
    #pragma unroll
    for (int i = 0; i < 8; ++i) { acc[i][0] = 0.f; acc[i][1] = 0.f; }

    int ml = t >> 2;
    int kl = (t & 3) * 4;
    int gm = rm + ml;
    bool mOk = gm < NNODES;
    int wk = t >> 4;
    int wj = (t & 15) * 4;

    for (int kt = 0; kt < D1; kt += 16) {
        if (mOk) {
            float4 s4 = *(const float4*)(g_side1 + (size_t)gm * D1 + kt + kl);
            float4 e4 = *(const float4*)(g_ego1  + (size_t)gm * D1 + kt + kl);
            As[kl + 0][ml] = s4.x + e4.x;  Hs[kl + 0][ml] = s4.x * e4.x;
            As[kl + 1][ml] = s4.y + e4.y;  Hs[kl + 1][ml] = s4.y * e4.y;
            As[kl + 2][ml] = s4.z + e4.z;  Hs[kl + 2][ml] = s4.z * e4.z;
            As[kl + 3][ml] = s4.w + e4.w;  Hs[kl + 3][ml] = s4.w * e4.w;
        } else {
            As[kl + 0][ml] = 0.f; Hs[kl + 0][ml] = 0.f;
            As[kl + 1][ml] = 0.f; Hs[kl + 1][ml] = 0.f;
            As[kl + 2][ml] = 0.f; Hs[kl + 2][ml] = 0.f;
            As[kl + 3][ml] = 0.f; Hs[kl + 3][ml] = 0.f;
        }
        *(float4*)&W1s[wk][wj] = *(const float4*)(W1 + (size_t)(kt + wk) * D2 + wj);
        *(float4*)&W2s[wk][wj] = *(const float4*)(W2 + (size_t)(kt + wk) * D2 + wj);
        __syncthreads();

        #pragma unroll
        for (int k = 0; k < 16; ++k) {
            float2 w1 = *(const float2*)&W1s[k][tx * 2];
            float2 w2 = *(const float2*)&W2s[k][tx * 2];
            float4 a0 = *(const float4*)&As[k][ty * 8];
            float4 a1 = *(const float4*)&As[k][ty * 8 + 4];
            float4 h0 = *(const float4*)&Hs[k][ty * 8];
            float4 h1 = *(const float4*)&Hs[k][ty * 8 + 4];
            float a[8] = {a0.x, a0.y, a0.z, a0.w, a1.x, a1.y, a1.z, a1.w};
            float h[8] = {h0.x, h0.y, h0.z, h0.w, h1.x, h1.y, h1.z, h1.w};
            #pragma unroll
            for (int i = 0; i < 8; ++i) {
                acc[i][0] += a[i] * w1.x + h[i] * w2.x;
                acc[i][1] += a[i] * w1.y + h[i] * w2.y;
            }
        }
        __syncthreads();
    }

    int jc = tx * 2;
    float bs0 = b1[jc] + b2[jc];
    float bs1 = b1[jc + 1] + b2[jc + 1];
    #pragma unroll
    for (int i = 0; i < 8; ++i) {
        int row = rm + ty * 8 + i;
        float v0 = leaky(acc[i][0] + bs0);
        float v1 = leaky(acc[i][1] + bs1);
        float ss = v0 * v0 + v1 * v1;
        #pragma unroll
        for (int off = 16; off > 0; off >>= 1)
            ss += __shfl_xor_sync(0xffffffffu, ss, off);
        float inv = 1.f / fmaxf(sqrtf(ss), 1e-12f);
        if (row < NNODES) {
            float2 o = make_float2(v0 * inv, v1 * inv);
            *(float2*)(out + (size_t)row * OUTW + (D0 + D1) + jc) = o;
        }
    }
}

// ---------------- launch ----------------
extern "C" void kernel_launch(void* const* d_in, const int* in_sizes, int n_in,
                              void* d_out, int out_size) {
    const float* item  = (const float*)d_in[0];
    const float* user  = (const float*)d_in[1];
    const float* W1_0  = (const float*)d_in[2];
    const float* b1_0  = (const float*)d_in[3];
    const float* W2_0  = (const float*)d_in[4];
    const float* b2_0  = (const float*)d_in[5];
    const float* W1_1  = (const float*)d_in[6];
    const float* b1_1  = (const float*)d_in[7];
    const float* W2_1  = (const float*)d_in[8];
    const float* b2_1  = (const float*)d_in[9];
    const float* evals = (const float*)d_in[10];
    const int*   erows = (const int*)d_in[11];
    const int*   ecols = (const int*)d_in[12];
    float* out = (float*)d_out;

    init_hist_kernel<<<64, 256>>>();
    hist_kernel<<<(NEDGES + 255) / 256, 256>>>(erows);
    scan_kernel<<<1, 1024>>>();
    scatter_kernel<<<(NEDGES + 255) / 256, 256>>>(erows, ecols, evals);
    wsplit_kernel<<<(D1 * D0 + 255) / 256, 256>>>(W1_0, W2_0);

    {
        dim3 grid((NNODES + 7) / 8, D0 / 256);   // y = feature chunk (slow dim)
        spmm0_chunk_kernel<<<grid, 256>>>(item, user);
    }
    gemm0_mma_kernel<<<(NNODES + 63) / 64, 128>>>(item, user, b1_0, b2_0, out);
    spmm1_kernel<<<(NNODES + 3) / 4, 128>>>();
    gemm1_kernel<<<(NNODES + 63) / 64, 256>>>(W1_1, b1_1, W2_1, b2_1, out);
}

// round 8
// speedup vs baseline: 1.0927x; 1.0927x over previous
#include <cuda_runtime.h>
#include <cuda_bf16.h>
#include <cstdint>

#define N_ITEMS 30000
#define N_USERS 20000
#define NNODES  50000
#define NEDGES  512000
#define D0 768
#define D1 128
#define D2 64
#define OUTW 960   // 768 + 128 + 64
#define SCANB ((NNODES + 1023) / 1024)   // 49

// ---------------- device scratch (static, no runtime alloc) ----------------
__device__ float g_side0[(size_t)NNODES * D0];   // 153.6 MB
__device__ float g_ego1 [(size_t)NNODES * D1];   // 25.6 MB
__device__ float g_side1[(size_t)NNODES * D1];   // 25.6 MB
__device__ int   g_hist[NNODES];
__device__ int   g_rowptr[NNODES + 1];
__device__ int   g_cursor[NNODES];
__device__ int   g_col_sorted[NEDGES];
__device__ float g_val_sorted[NEDGES];
__device__ int   g_bsum[64];
__device__ int   g_boff[64];
// split + transposed weights for tensor-core gemm0: [N=128][K=768] bf16
__device__ __nv_bfloat16 g_w1hiT[D1 * D0];
__device__ __nv_bfloat16 g_w1loT[D1 * D0];
__device__ __nv_bfloat16 g_w2hiT[D1 * D0];
__device__ __nv_bfloat16 g_w2loT[D1 * D0];

__device__ __forceinline__ float leaky(float v) { return v > 0.f ? v : 0.01f * v; }

__device__ __forceinline__ uint32_t smem_u32(const void* p) {
    uint32_t a;
    asm("{ .reg .u64 t; cvta.to.shared.u64 t, %1; cvt.u32.u64 %0, t; }"
        : "=r"(a) : "l"(p));
    return a;
}
__device__ __forceinline__ void ldsm_x4(uint32_t* r, uint32_t addr) {
    asm volatile("ldmatrix.sync.aligned.m8n8.x4.shared.b16 {%0,%1,%2,%3}, [%4];"
                 : "=r"(r[0]), "=r"(r[1]), "=r"(r[2]), "=r"(r[3]) : "r"(addr));
}
__device__ __forceinline__ void ldsm_x2(uint32_t* r, uint32_t addr) {
    asm volatile("ldmatrix.sync.aligned.m8n8.x2.shared.b16 {%0,%1}, [%2];"
                 : "=r"(r[0]), "=r"(r[1]) : "r"(addr));
}
__device__ __forceinline__ void mma_bf16(float* d, const uint32_t* a, const uint32_t* b) {
    asm volatile(
        "mma.sync.aligned.m16n8k16.row.col.f32.bf16.bf16.f32 "
        "{%0,%1,%2,%3}, {%4,%5,%6,%7}, {%8,%9}, {%0,%1,%2,%3};"
        : "+f"(d[0]), "+f"(d[1]), "+f"(d[2]), "+f"(d[3])
        : "r"(a[0]), "r"(a[1]), "r"(a[2]), "r"(a[3]), "r"(b[0]), "r"(b[1]));
}
__device__ __forceinline__ uint32_t pack_bf16(__nv_bfloat16 a, __nv_bfloat16 b) {
    return ((uint32_t)__bfloat16_as_ushort(b) << 16) | (uint32_t)__bfloat16_as_ushort(a);
}
__device__ __forceinline__ void split_bf16(float x, __nv_bfloat16& hi, __nv_bfloat16& lo) {
    hi = __float2bfloat16(x);
    lo = __float2bfloat16(x - __bfloat162float(hi));
}

// ---------------- CSR build ----------------
__global__ void init_hist_kernel() {
    for (int i = blockIdx.x * blockDim.x + threadIdx.x; i < NNODES;
         i += gridDim.x * blockDim.x)
        g_hist[i] = 0;
}

__global__ void hist_kernel(const int* __restrict__ rows) {
    int e = blockIdx.x * blockDim.x + threadIdx.x;
    if (e < NEDGES) atomicAdd(&g_hist[rows[e]], 1);
}

// multi-block scan: local exclusive scans + block totals
__global__ void scan_local_kernel() {
    __shared__ int wsum[32];
    int tid = threadIdx.x, lane = tid & 31, wid = tid >> 5;
    int i = blockIdx.x * 1024 + tid;
    int v = (i < NNODES) ? g_hist[i] : 0;
    int x = v;
    #pragma unroll
    for (int off = 1; off < 32; off <<= 1) {
        int t = __shfl_up_sync(0xffffffffu, x, off);
        if (lane >= off) x += t;
    }
    if (lane == 31) wsum[wid] = x;
    __syncthreads();
    if (wid == 0) {
        int w = wsum[lane];
        #pragma unroll
        for (int off = 1; off < 32; off <<= 1) {
            int t = __shfl_up_sync(0xffffffffu, w, off);
            if (lane >= off) w += t;
        }
        wsum[lane] = w;
    }
    __syncthreads();
    int warp_off = (wid == 0) ? 0 : wsum[wid - 1];
    int incl = x + warp_off;
    if (i < NNODES) g_rowptr[i] = incl - v;      // block-local exclusive
    if (tid == 1023) g_bsum[blockIdx.x] = incl;  // block total
}

__global__ void scan_bsum_kernel() {   // 1 block, 64 threads
    __shared__ int s[64];
    int tid = threadIdx.x;
    int v = (tid < SCANB) ? g_bsum[tid] : 0;
    s[tid] = v;
    __syncthreads();
    #pragma unroll
    for (int off = 1; off < 64; off <<= 1) {
        int t = (tid >= off) ? s[tid - off] : 0;
        __syncthreads();
        s[tid] += t;
        __syncthreads();
    }
    g_boff[tid] = s[tid] - v;
    if (tid == SCANB - 1) g_rowptr[NNODES] = s[tid];
}

__global__ void scan_add_kernel() {    // grid SCANB, block 1024 (same mapping)
    int i = blockIdx.x * 1024 + threadIdx.x;
    if (i < NNODES) {
        int val = g_rowptr[i] + g_boff[blockIdx.x];
        g_rowptr[i] = val;
        g_cursor[i] = val;
    }
}

__global__ void scatter_kernel(const int* __restrict__ rows,
                               const int* __restrict__ cols,
                               const float* __restrict__ vals) {
    int e = blockIdx.x * blockDim.x + threadIdx.x;
    if (e < NEDGES) {
        int r = rows[e];
        int p = atomicAdd(&g_cursor[r], 1);
        g_col_sorted[p] = cols[e];
        g_val_sorted[p] = vals[e];
    }
}

// ---------------- W split+transpose prep ----------------
__global__ void wsplit_kernel(const float* __restrict__ W1,
                              const float* __restrict__ W2) {
    int idx = blockIdx.x * blockDim.x + threadIdx.x;   // over 128*768, k fast
    if (idx >= D1 * D0) return;
    int n = idx / D0, k = idx - n * D0;
    float w1 = W1[(size_t)k * D1 + n];
    float w2 = W2[(size_t)k * D1 + n];
    __nv_bfloat16 hi, lo;
    split_bf16(w1, hi, lo);
    g_w1hiT[idx] = hi; g_w1loT[idx] = lo;
    split_bf16(w2, hi, lo);
    g_w2hiT[idx] = hi; g_w2loT[idx] = lo;
}

// ---------------- SpMM layer0 (128-wide chunks, unroll 8) ----------------
// side0[:, kt:kt+128] = A @ ego0[:, kt:kt+128]; blockIdx.y = chunk (slow dim).
__global__ __launch_bounds__(256) void spmm0_chunk_kernel(
    const float* __restrict__ item, const float* __restrict__ user) {
    const int w = threadIdx.x >> 5;      // warp -> row
    const int lane = threadIdx.x & 31;   // lane -> 4 cols
    const int r = blockIdx.x * 8 + w;
    const int off = blockIdx.y * 128 + lane * 4;
    if (r >= NNODES) return;
    const int e0 = g_rowptr[r], e1 = g_rowptr[r + 1];
    float4 acc = make_float4(0.f, 0.f, 0.f, 0.f);
    int e = e0;
    const int n8 = e0 + ((e1 - e0) & ~7);
    for (; e < n8; e += 8) {
        const float* p[8];
        float v[8];
        #pragma unroll
        for (int q = 0; q < 8; ++q) {
            int c = g_col_sorted[e + q];
            v[q] = g_val_sorted[e + q];
            p[q] = ((c < N_ITEMS) ? item + (size_t)c * D0
                                  : user + (size_t)(c - N_ITEMS) * D0) + off;
        }
        float4 x[8];
        #pragma unroll
        for (int q = 0; q < 8; ++q) x[q] = __ldg((const float4*)p[q]);
        #pragma unroll
        for (int q = 0; q < 8; ++q) {
            acc.x += v[q] * x[q].x;
            acc.y += v[q] * x[q].y;
            acc.z += v[q] * x[q].z;
            acc.w += v[q] * x[q].w;
        }
    }
    for (; e < e1; ++e) {
        int   c = g_col_sorted[e];
        float v = g_val_sorted[e];
        const float* p = ((c < N_ITEMS) ? item + (size_t)c * D0
                                        : user + (size_t)(c - N_ITEMS) * D0) + off;
        float4 x = __ldg((const float4*)p);
        acc.x += v * x.x; acc.y += v * x.y; acc.z += v * x.z; acc.w += v * x.w;
    }
    *(float4*)(g_side0 + (size_t)r * D0 + off) = acc;
}

// ---------------- fused GEMM layer0 (mma.sync bf16, 3-term split) ----------------
// ego1 = leaky((side0+ego0)@W1 + b1 + (side0*ego0)@W2 + b2)
// Streams ego0 -> out[:, 0:768]; fuses row-normalize -> out[:, 768:896].
// BM=64, BN=128, BK=16, 128 threads (4 warps 2x2, warp tile 32x64)
#define APAD 24   // row stride in bf16 (48 B, conflict-free ldmatrix)

__global__ __launch_bounds__(128) void gemm0_mma_kernel(
    const float* __restrict__ item, const float* __restrict__ user,
    const float* __restrict__ b1, const float* __restrict__ b2,
    float* __restrict__ out) {
    __shared__ __align__(16) __nv_bfloat16 sAhi[64 * APAD];
    __shared__ __align__(16) __nv_bfloat16 sAlo[64 * APAD];
    __shared__ __align__(16) __nv_bfloat16 sHhi[64 * APAD];
    __shared__ __align__(16) __nv_bfloat16 sHlo[64 * APAD];
    __shared__ __align__(16) __nv_bfloat16 sW1h[128 * APAD];
    __shared__ __align__(16) __nv_bfloat16 sW1l[128 * APAD];
    __shared__ __align__(16) __nv_bfloat16 sW2h[128 * APAD];
    __shared__ __align__(16) __nv_bfloat16 sW2l[128 * APAD];
    __shared__ float bsum[D1];
    __shared__ float rowss[64];

    const int t    = threadIdx.x;
    const int lane = t & 31;
    const int wid  = t >> 5;
    const int wm   = wid >> 1;           // 0..1 -> M offset wm*32
    const int wn   = wid & 1;            // 0..1 -> N offset wn*64
    const int rm   = blockIdx.x * 64;

    bsum[t] = b1[t] + b2[t];
    if (t < 64) rowss[t] = 0.f;

    // per-thread staging coords
    const int arow = t >> 1;             // 0..63
    const int akq  = (t & 1) * 8;        // 0 or 8
    const int gm   = rm + arow;
    const bool mOk = gm < NNODES;
    const float* sideRow = g_side0 + (size_t)gm * D0 + akq;
    const float* egoRow  = ((gm < N_ITEMS) ? item + (size_t)gm * D0
                                           : user + (size_t)(gm - N_ITEMS) * D0) + akq;
    float* outRow = out + (size_t)gm * OUTW + akq;

    // ldmatrix addresses (constant across k-chunks)
    const uint32_t aOff = (uint32_t)(((wm * 32 + (lane & 15)) * APAD + (lane >> 4) * 8) * 2);
    const uint32_t addrAhi = smem_u32(sAhi) + aOff;
    const uint32_t addrAlo = smem_u32(sAlo) + aOff;
    const uint32_t addrHhi = smem_u32(sHhi) + aOff;
    const uint32_t addrHlo = smem_u32(sHlo) + aOff;
    const uint32_t bOff = (uint32_t)(((wn * 64 + (lane & 7)) * APAD + ((lane >> 3) & 1) * 8) * 2);
    const uint32_t addrW1h = smem_u32(sW1h) + bOff;
    const uint32_t addrW1l = smem_u32(sW1l) + bOff;
    const uint32_t addrW2h = smem_u32(sW2h) + bOff;
    const uint32_t addrW2l = smem_u32(sW2l) + bOff;
    const uint32_t MT = 16 * APAD * 2;   // m-tile stride bytes
    const uint32_t JT = 8 * APAD * 2;    // n-tile stride bytes

    float acc[2][8][4];
    #pragma unroll
    for (int i = 0; i < 2; ++i)
        #pragma unroll
        for (int j = 0; j < 8; ++j)
            #pragma unroll
            for (int q = 0; q < 4; ++q) acc[i][j][q] = 0.f;

    for (int kt = 0; kt < D0; kt += 16) {
        // ---- stage A variants (+ stream ego to out[:, 0:768]) ----
        {
            float4 sa, sb, ea, eb;
            if (mOk) {
                sa = __ldg((const float4*)(sideRow + kt));
                sb = __ldg((const float4*)(sideRow + kt + 4));
                ea = __ldg((const float4*)(egoRow + kt));
                eb = __ldg((const float4*)(egoRow + kt + 4));
                *(float4*)(outRow + kt) = ea;
                *(float4*)(outRow + kt + 4) = eb;
            } else {
                sa = make_float4(0.f, 0.f, 0.f, 0.f);
                sb = sa; ea = sa; eb = sa;
            }
            float av[8] = {sa.x + ea.x, sa.y + ea.y, sa.z + ea.z, sa.w + ea.w,
                           sb.x + eb.x, sb.y + eb.y, sb.z + eb.z, sb.w + eb.w};
            float hv[8] = {sa.x * ea.x, sa.y * ea.y, sa.z * ea.z, sa.w * ea.w,
                           sb.x * eb.x, sb.y * eb.y, sb.z * eb.z, sb.w * eb.w};
            uint4 uahi, ualo, uhhi, uhlo;
            uint32_t* pa = (uint32_t*)&uahi; uint32_t* pl = (uint32_t*)&ualo;
            uint32_t* ph = (uint32_t*)&uhhi; uint32_t* pm = (uint32_t*)&uhlo;
            __nv_bfloat16 h0, l0, h1, l1;
            #pragma unroll
            for (int q = 0; q < 4; ++q) {
                split_bf16(av[2 * q], h0, l0);
                split_bf16(av[2 * q + 1], h1, l1);
                pa[q] = pack_bf16(h0, h1);
                pl[q] = pack_bf16(l0, l1);
                split_bf16(hv[2 * q], h0, l0);
                split_bf16(hv[2 * q + 1], h1, l1);
                ph[q] = pack_bf16(h0, h1);
                pm[q] = pack_bf16(l0, l1);
            }
            int d = arow * APAD + akq;
            *(uint4*)(sAhi + d) = uahi;
            *(uint4*)(sAlo + d) = ualo;
            *(uint4*)(sHhi + d) = uhhi;
            *(uint4*)(sHlo + d) = uhlo;
        }
        // ---- stage W variants ----
        #pragma unroll
        for (int s = 0; s < 2; ++s) {
            int g = s * 128 + t;
            int n = g >> 1;
            int kq = (g & 1) * 8;
            size_t src = (size_t)n * D0 + kt + kq;
            int d = n * APAD + kq;
            *(uint4*)(sW1h + d) = __ldg((const uint4*)(g_w1hiT + src));
            *(uint4*)(sW1l + d) = __ldg((const uint4*)(g_w1loT + src));
            *(uint4*)(sW2h + d) = __ldg((const uint4*)(g_w2hiT + src));
            *(uint4*)(sW2l + d) = __ldg((const uint4*)(g_w2loT + src));
        }
        __syncthreads();

        // ---- A fragments (4 variants x 2 m-tiles) ----
        uint32_t fAhi[2][4], fAlo[2][4], fHhi[2][4], fHlo[2][4];
        ldsm_x4(fAhi[0], addrAhi);       ldsm_x4(fAhi[1], addrAhi + MT);
        ldsm_x4(fAlo[0], addrAlo);       ldsm_x4(fAlo[1], addrAlo + MT);
        ldsm_x4(fHhi[0], addrHhi);       ldsm_x4(fHhi[1], addrHhi + MT);
        ldsm_x4(fHlo[0], addrHlo);       ldsm_x4(fHlo[1], addrHlo + MT);

        #pragma unroll
        for (int j = 0; j < 8; ++j) {
            uint32_t b[2];
            ldsm_x2(b, addrW1h + j * JT);
            mma_bf16(acc[0][j], fAhi[0], b);
            mma_bf16(acc[1][j], fAhi[1], b);
            mma_bf16(acc[0][j], fAlo[0], b);
            mma_bf16(acc[1][j], fAlo[1], b);
            ldsm_x2(b, addrW1l + j * JT);
            mma_bf16(acc[0][j], fAhi[0], b);
            mma_bf16(acc[1][j], fAhi[1], b);
            ldsm_x2(b, addrW2h + j * JT);
            mma_bf16(acc[0][j], fHhi[0], b);
            mma_bf16(acc[1][j], fHhi[1], b);
            mma_bf16(acc[0][j], fHlo[0], b);
            mma_bf16(acc[1][j], fHlo[1], b);
            ldsm_x2(b, addrW2l + j * JT);
            mma_bf16(acc[0][j], fHhi[0], b);
            mma_bf16(acc[1][j], fHhi[1], b);
        }
        __syncthreads();
    }

    // ---- epilogue: bias + leaky -> regs, row sum-of-squares -> smem ----
    float vals[2][8][4];
    #pragma unroll
    for (int mt = 0; mt < 2; ++mt) {
        float s0 = 0.f, s1 = 0.f;
        #pragma unroll
        for (int j = 0; j < 8; ++j) {
            int col = wn * 64 + j * 8 + (lane & 3) * 2;
            float bc0 = bsum[col], bc1 = bsum[col + 1];
            float v0 = leaky(acc[mt][j][0] + bc0);
            float v1 = leaky(acc[mt][j][1] + bc1);
            float v2 = leaky(acc[mt][j][2] + bc0);
            float v3 = leaky(acc[mt][j][3] + bc1);
            vals[mt][j][0] = v0; vals[mt][j][1] = v1;
            vals[mt][j][2] = v2; vals[mt][j][3] = v3;
            s0 += v0 * v0 + v1 * v1;
            s1 += v2 * v2 + v3 * v3;
        }
        int lr0 = wm * 32 + mt * 16 + (lane >> 2);
        atomicAdd(&rowss[lr0], s0);
        atomicAdd(&rowss[lr0 + 8], s1);
    }
    __syncthreads();

    // ---- write raw ego1 + normalized out[:, 768:896] ----
    #pragma unroll
    for (int mt = 0; mt < 2; ++mt) {
        int lr0 = wm * 32 + mt * 16 + (lane >> 2);
        int row0 = rm + lr0;
        int row1 = row0 + 8;
        float inv0 = 1.f / fmaxf(sqrtf(rowss[lr0]), 1e-12f);
        float inv1 = 1.f / fmaxf(sqrtf(rowss[lr0 + 8]), 1e-12f);
        #pragma unroll
        for (int j = 0; j < 8; ++j) {
            int col = wn * 64 + j * 8 + (lane & 3) * 2;
            if (row0 < NNODES) {
                float2 o = make_float2(vals[mt][j][0], vals[mt][j][1]);
                *(float2*)(g_ego1 + (size_t)row0 * D1 + col) = o;
                float2 n = make_float2(o.x * inv0, o.y * inv0);
                *(float2*)(out + (size_t)row0 * OUTW + D0 + col) = n;
            }
            if (row1 < NNODES) {
                float2 o = make_float2(vals[mt][j][2], vals[mt][j][3]);
                *(float2*)(g_ego1 + (size_t)row1 * D1 + col) = o;
                float2 n = make_float2(o.x * inv1, o.y * inv1);
                *(float2*)(out + (size_t)row1 * OUTW + D0 + col) = n;
            }
        }
    }
}

// ---------------- SpMM layer1: side1 = A @ ego1 (unroll 4) ----------------
__global__ void spmm1_kernel() {
    int w = threadIdx.x >> 5;
    int lane = threadIdx.x & 31;
    int r = blockIdx.x * 4 + w;
    if (r >= NNODES) return;
    int e0 = g_rowptr[r], e1 = g_rowptr[r + 1];
    float4 acc = make_float4(0.f, 0.f, 0.f, 0.f);
    int e = e0;
    int n4 = e0 + ((e1 - e0) & ~3);
    for (; e < n4; e += 4) {
        int c0 = g_col_sorted[e + 0], c1 = g_col_sorted[e + 1];
        int c2 = g_col_sorted[e + 2], c3 = g_col_sorted[e + 3];
        float v0 = g_val_sorted[e + 0], v1 = g_val_sorted[e + 1];
        float v2 = g_val_sorted[e + 2], v3 = g_val_sorted[e + 3];
        float4 x0 = __ldg((const float4*)g_ego1 + (size_t)c0 * (D1 / 4) + lane);
        float4 x1 = __ldg((const float4*)g_ego1 + (size_t)c1 * (D1 / 4) + lane);
        float4 x2 = __ldg((const float4*)g_ego1 + (size_t)c2 * (D1 / 4) + lane);
        float4 x3 = __ldg((const float4*)g_ego1 + (size_t)c3 * (D1 / 4) + lane);
        acc.x += v0 * x0.x + v1 * x1.x + v2 * x2.x + v3 * x3.x;
        acc.y += v0 * x0.y + v1 * x1.y + v2 * x2.y + v3 * x3.y;
        acc.z += v0 * x0.z + v1 * x1.z + v2 * x2.z + v3 * x3.z;
        acc.w += v0 * x0.w + v1 * x1.w + v2 * x2.w + v3 * x3.w;
    }
    for (; e < e1; ++e) {
        int   c = g_col_sorted[e];
        float v = g_val_sorted[e];
        float4 x = __ldg((const float4*)g_ego1 + (size_t)c * (D1 / 4) + lane);
        acc.x += v * x.x; acc.y += v * x.y; acc.z += v * x.z; acc.w += v * x.w;
    }
    ((float4*)g_side1)[(size_t)r * (D1 / 4) + lane] = acc;
}

// ---------------- fused GEMM layer1 + normalize -> out[:, 896:960] ----------------
__global__ __launch_bounds__(256) void gemm1_kernel(
    const float* __restrict__ W1, const float* __restrict__ b1,
    const float* __restrict__ W2, const float* __restrict__ b2,
    float* __restrict__ out) {
    __shared__ __align__(16) float As[16][68];
    __shared__ __align__(16) float Hs[16][68];
    __shared__ __align__(16) float W1s[16][64];
    __shared__ __align__(16) float W2s[16][64];

    int t  = threadIdx.x;
    int tx = t & 31, ty = t >> 5;
    int rm = blockIdx.x * 64;

    float acc[8][2];
    #pragma unroll
    for (int i = 0; i < 8; ++i) { acc[i][0] = 0.f; acc[i][1] = 0.f; }

    int ml = t >> 2;
    int kl = (t & 3) * 4;
    int gm = rm + ml;
    bool mOk = gm < NNODES;
    int wk = t >> 4;
    int wj = (t & 15) * 4;

    for (int kt = 0; kt < D1; kt += 16) {
        if (mOk) {
            float4 s4 = *(const float4*)(g_side1 + (size_t)gm * D1 + kt + kl);
            float4 e4 = *(const float4*)(g_ego1  + (size_t)gm * D1 + kt + kl);
            As[kl + 0][ml] = s4.x + e4.x;  Hs[kl + 0][ml] = s4.x * e4.x;
            As[kl + 1][ml] = s4.y + e4.y;  Hs[kl + 1][ml] = s4.y * e4.y;
            As[kl + 2][ml] = s4.z + e4.z;  Hs[kl + 2][ml] = s4.z * e4.z;
            As[kl + 3][ml] = s4.w + e4.w;  Hs[kl + 3][ml] = s4.w * e4.w;
        } else {
            As[kl + 0][ml] = 0.f; Hs[kl + 0][ml] = 0.f;
            As[kl + 1][ml] = 0.f; Hs[kl + 1][ml] = 0.f;
            As[kl + 2][ml] = 0.f; Hs[kl + 2][ml] = 0.f;
            As[kl + 3][ml] = 0.f; Hs[kl + 3][ml] = 0.f;
        }
        *(float4*)&W1s[wk][wj] = *(const float4*)(W1 + (size_t)(kt + wk) * D2 + wj);
        *(float4*)&W2s[wk][wj] = *(const float4*)(W2 + (size_t)(kt + wk) * D2 + wj);
        __syncthreads();

        #pragma unroll
        for (int k = 0; k < 16; ++k) {
            float2 w1 = *(const float2*)&W1s[k][tx * 2];
            float2 w2 = *(const float2*)&W2s[k][tx * 2];
            float4 a0 = *(const float4*)&As[k][ty * 8];
            float4 a1 = *(const float4*)&As[k][ty * 8 + 4];
            float4 h0 = *(const float4*)&Hs[k][ty * 8];
            float4 h1 = *(const float4*)&Hs[k][ty * 8 + 4];
            float a[8] = {a0.x, a0.y, a0.z, a0.w, a1.x, a1.y, a1.z, a1.w};
            float h[8] = {h0.x, h0.y, h0.z, h0.w, h1.x, h1.y, h1.z, h1.w};
            #pragma unroll
            for (int i = 0; i < 8; ++i) {
                acc[i][0] += a[i] * w1.x + h[i] * w2.x;
                acc[i][1] += a[i] * w1.y + h[i] * w2.y;
            }
        }
        __syncthreads();
    }

    int jc = tx * 2;
    float bs0 = b1[jc] + b2[jc];
    float bs1 = b1[jc + 1] + b2[jc + 1];
    #pragma unroll
    for (int i = 0; i < 8; ++i) {
        int row = rm + ty * 8 + i;
        float v0 = leaky(acc[i][0] + bs0);
        float v1 = leaky(acc[i][1] + bs1);
        float ss = v0 * v0 + v1 * v1;
        #pragma unroll
        for (int off = 16; off > 0; off >>= 1)
            ss += __shfl_xor_sync(0xffffffffu, ss, off);
        float inv = 1.f / fmaxf(sqrtf(ss), 1e-12f);
        if (row < NNODES) {
            float2 o = make_float2(v0 * inv, v1 * inv);
            *(float2*)(out + (size_t)row * OUTW + (D0 + D1) + jc) = o;
        }
    }
}

// ---------------- launch ----------------
extern "C" void kernel_launch(void* const* d_in, const int* in_sizes, int n_in,
                              void* d_out, int out_size) {
    const float* item  = (const float*)d_in[0];
    const float* user  = (const float*)d_in[1];
    const float* W1_0  = (const float*)d_in[2];
    const float* b1_0  = (const float*)d_in[3];
    const float* W2_0  = (const float*)d_in[4];
    const float* b2_0  = (const float*)d_in[5];
    const float* W1_1  = (const float*)d_in[6];
    const float* b1_1  = (const float*)d_in[7];
    const float* W2_1  = (const float*)d_in[8];
    const float* b2_1  = (const float*)d_in[9];
    const float* evals = (const float*)d_in[10];
    const int*   erows = (const int*)d_in[11];
    const int*   ecols = (const int*)d_in[12];
    float* out = (float*)d_out;

    init_hist_kernel<<<64, 256>>>();
    hist_kernel<<<(NEDGES + 255) / 256, 256>>>(erows);
    scan_local_kernel<<<SCANB, 1024>>>();
    scan_bsum_kernel<<<1, 64>>>();
    scan_add_kernel<<<SCANB, 1024>>>();
    scatter_kernel<<<(NEDGES + 255) / 256, 256>>>(erows, ecols, evals);
    wsplit_kernel<<<(D1 * D0 + 255) / 256, 256>>>(W1_0, W2_0);

    {
        dim3 grid((NNODES + 7) / 8, D0 / 128);   // y = feature chunk (slow dim)
        spmm0_chunk_kernel<<<grid, 256>>>(item, user);
    }
    gemm0_mma_kernel<<<(NNODES + 63) / 64, 128>>>(item, user, b1_0, b2_0, out);
    spmm1_kernel<<<(NNODES + 3) / 4, 128>>>();
    gemm1_kernel<<<(NNODES + 63) / 64, 256>>>(W1_1, b1_1, W2_1, b2_1, out);
}